// round 11
// baseline (speedup 1.0000x reference)
#include <cuda_runtime.h>
#include <cuda_fp16.h>
#include <cstdint>

#define TT 4
#define NN 50000
#define DH 64
#define EE 800000
#define ROWS (TT*NN)       // 200000
#define NBANK 64
#define BN_EPS 1e-5f
#define SCAN_BLOCKS 196    // ceil(50000/256)
#define CSR_CAP (EE + 8*NN)

// ---------------- device scratch (static, no allocs) ----------------
__device__ __align__(16) __half d_xh[(size_t)ROWS*DH];    // fp16 node_data
__device__ __align__(16) __half d_avgh[(size_t)ROWS*DH];  // fp16 avg_neighbor
__device__ int   d_cnt[NN];
__device__ int   d_offs[NN];
__device__ int   d_cursor[NN];
__device__ float d_Z[NN];
__device__ int   d_alloc_ctr;
__device__ __align__(16) int2 d_csr[CSR_CAP];             // {src, w-bits}, padded per node
// banks: [bank][stat][col]: 0 sumAll,1 sqAll,2 sumLast,3 sqLast,4 sumAvg,5 sqAvg
__device__ float d_banks[NBANK*6*64];
__device__ __align__(16) uint4 d_Wfrag[1536];             // m16n8k16 B-fragment order
__device__ __align__(16) float d_bp[64];

__device__ __forceinline__ uint32_t smem_u32(const void* p) {
    uint32_t a;
    asm("{ .reg .u64 t; cvta.to.shared.u64 t, %1; cvt.u32.u64 %0, t; }" : "=r"(a) : "l"(p));
    return a;
}

// ---------------- kernels ----------------
__global__ void k_zero() {
    int i = blockIdx.x*256 + threadIdx.x;
    if (i < NN) { d_cnt[i] = 0; d_Z[i] = 0.f; }
    if (i < NBANK*6*64) d_banks[i] = 0.f;
    if (i == 0) d_alloc_ctr = 0;
}

__global__ void k_hist(const float* __restrict__ ew, const int* __restrict__ dst) {
    int base = blockIdx.x*1024 + threadIdx.x;
    int   dd[4]; float ww[4]; bool v[4];
    #pragma unroll
    for (int k = 0; k < 4; k++) {
        int e = base + k*256;
        v[k] = (e < EE);
        if (v[k]) { dd[k] = dst[e]; ww[k] = ew[e]; }
    }
    #pragma unroll
    for (int k = 0; k < 4; k++)
        if (v[k]) { atomicAdd(&d_cnt[dd[k]], 1); atomicAdd(&d_Z[dd[k]], ww[k]); }
}

// segment allocation: order-free CSR offsets via warp-aggregated atomic.
// Pads each node's segment to a multiple of 8 with {0, w=0} edges.
__global__ void k_alloc() {
    int i = blockIdx.x*256 + threadIdx.x;
    int lane = threadIdx.x & 31;
    int c  = (i < NN) ? d_cnt[i] : 0;
    int cp = (c + 7) & ~7;
    int incl = cp;
    #pragma unroll
    for (int s = 1; s < 32; s <<= 1) {
        int t = __shfl_up_sync(0xffffffffu, incl, s);
        if (lane >= s) incl += t;
    }
    int total = __shfl_sync(0xffffffffu, incl, 31);
    int base = 0;
    if (lane == 31) base = atomicAdd(&d_alloc_ctr, total);
    base = __shfl_sync(0xffffffffu, base, 31);
    int off = base + incl - cp;
    if (i < NN) {
        d_offs[i] = off;
        d_cursor[i] = off;
        for (int p = c; p < cp; p++) d_csr[off + p] = make_int2(0, 0);
    }
}

__global__ void k_fill(const float* __restrict__ ew, const int* __restrict__ src,
                       const int* __restrict__ dst) {
    int base = blockIdx.x*1024 + threadIdx.x;
    int ss[4], dd[4]; float ww[4]; bool v[4];
    #pragma unroll
    for (int k = 0; k < 4; k++) {
        int e = base + k*256;
        v[k] = (e < EE);
        if (v[k]) { ss[k] = src[e]; dd[k] = dst[e]; ww[k] = ew[e]; }
    }
    #pragma unroll
    for (int k = 0; k < 4; k++)
        if (v[k]) {
            int p = atomicAdd(&d_cursor[dd[k]], 1);
            d_csr[p] = make_int2(ss[k], __float_as_int(ww[k]));
        }
}

// stage fp32 -> fp16 + column stats (single pass)
__global__ void __launch_bounds__(256) k_stage(const float* __restrict__ x) {
    int tid = blockIdx.x*256 + threadIdx.x;
    const int stride = 512*256;                  // divisible by 32
    const int lastBase = 3*NN*32;
    const float2* x2 = (const float2*)x;
    unsigned* xh2 = (unsigned*)d_xh;
    float s0=0.f,q0=0.f,l0=0.f,m0=0.f, s1=0.f,q1=0.f,l1=0.f,m1=0.f;
    for (int i = tid; i < ROWS*32; i += stride) {
        float2 v = x2[i];
        __half2 h = __floats2half2_rn(v.x, v.y);
        xh2[i] = *(unsigned*)&h;
        s0 += v.x; q0 += v.x*v.x; s1 += v.y; q1 += v.y*v.y;
        if (i >= lastBase) { l0 += v.x; m0 += v.x*v.x; l1 += v.y; m1 += v.y*v.y; }
    }
    __shared__ float sh[4][64];
    int col = (threadIdx.x & 31)*2;
    ((float*)sh)[threadIdx.x] = 0.f;
    __syncthreads();
    atomicAdd(&sh[0][col], s0); atomicAdd(&sh[0][col+1], s1);
    atomicAdd(&sh[1][col], q0); atomicAdd(&sh[1][col+1], q1);
    atomicAdd(&sh[2][col], l0); atomicAdd(&sh[2][col+1], l1);
    atomicAdd(&sh[3][col], m0); atomicAdd(&sh[3][col+1], m1);
    __syncthreads();
    if (threadIdx.x < 64) {
        float* b = d_banks + (blockIdx.x & (NBANK-1))*(6*64);
        atomicAdd(&b[0*64 + threadIdx.x], sh[0][threadIdx.x]);
        atomicAdd(&b[1*64 + threadIdx.x], sh[1][threadIdx.x]);
        atomicAdd(&b[2*64 + threadIdx.x], sh[2][threadIdx.x]);
        atomicAdd(&b[3*64 + threadIdx.x], sh[3][threadIdx.x]);
    }
}

// gather aggregation: warp per (node, timestep-pair). half=0 -> t{0,1}, half=1 -> t{2,3}.
// Halves the serial edge chain per warp (straggler tail) and the accumulator
// register pressure vs warp-per-node.
__global__ void __launch_bounds__(256) k_agg() {
    int w    = blockIdx.x*8 + (threadIdx.x >> 5);
    int n    = w >> 1;
    int half = w & 1;
    int lane = threadIdx.x & 31;
    __shared__ float sv[64], sq[64];
    if (threadIdx.x < 64) { sv[threadIdx.x] = 0.f; sq[threadIdx.x] = 0.f; }
    __syncthreads();
    if (n < NN) {
        const unsigned* xh2 = (const unsigned*)d_xh + (size_t)half*2*NN*32;
        int e0 = d_offs[n];
        int e1 = e0 + ((d_cnt[n] + 7) & ~7);     // padded end
        float2 a0 = make_float2(0.f,0.f), a1 = a0;
        for (int base = e0; base < e1; base += 32) {
            int m = e1 - base; if (m > 32) m = 32;    // multiple of 8
            int2 sw = (lane < m) ? d_csr[base+lane] : make_int2(0,0);
            for (int kb = 0; kb < m; kb += 8) {
                #pragma unroll
                for (int kk = 0; kk < 8; kk++) {
                    int k = kb + kk;
                    int   sk = __shfl_sync(0xffffffffu, sw.x, k);
                    float wk = __int_as_float(__shfl_sync(0xffffffffu, sw.y, k));
                    size_t ad = (size_t)sk*32 + lane;
                    unsigned u0 = xh2[ad];
                    unsigned u1 = xh2[(size_t)NN*32 + ad];
                    float2 v0 = __half22float2(*(__half2*)&u0);
                    float2 v1 = __half22float2(*(__half2*)&u1);
                    a0.x = fmaf(wk, v0.x, a0.x); a0.y = fmaf(wk, v0.y, a0.y);
                    a1.x = fmaf(wk, v1.x, a1.x); a1.y = fmaf(wk, v1.y, a1.y);
                }
            }
        }
        float z = d_Z[n];
        float inv = (z == 0.f) ? 1.f : 1.f/z;     // matches reference Z[Z==0]=1
        a0.x *= inv; a0.y *= inv; a1.x *= inv; a1.y *= inv;
        unsigned* av = (unsigned*)d_avgh + (size_t)half*2*NN*32;
        size_t nb = (size_t)n*32 + lane;
        __half2 h0 = __floats2half2_rn(a0.x, a0.y);
        __half2 h1 = __floats2half2_rn(a1.x, a1.y);
        av[nb]                 = *(unsigned*)&h0;
        av[(size_t)NN*32 + nb] = *(unsigned*)&h1;
        atomicAdd(&sv[2*lane],   a0.x + a1.x);
        atomicAdd(&sv[2*lane+1], a0.y + a1.y);
        atomicAdd(&sq[2*lane],   a0.x*a0.x + a1.x*a1.x);
        atomicAdd(&sq[2*lane+1], a0.y*a0.y + a1.y*a1.y);
    }
    __syncthreads();
    if (threadIdx.x < 64) {
        float* b = d_banks + (blockIdx.x & (NBANK-1))*(6*64);
        atomicAdd(&b[4*64 + threadIdx.x], sv[threadIdx.x]);
        atomicAdd(&b[5*64 + threadIdx.x], sq[threadIdx.x]);
    }
}

__device__ __forceinline__ unsigned pack_h2(float lo, float hi) {
    __half2 h = __floats2half2_rn(lo, hi);
    return *(unsigned*)&h;
}

// fold BN into GEMM: fp16 fragment-packed W' (m16n8k16) and fp32 b'
__global__ void k_finalize(const float* __restrict__ W1, const float* __restrict__ b1,
                           const float* __restrict__ gamma, const float* __restrict__ beta) {
    __shared__ float stat[6*64];
    __shared__ float s[192];
    __shared__ float tt[192];
    int tid = threadIdx.x;
    for (int k = tid; k < 6*64; k += 256) {
        float acc = 0.f;
        for (int b = 0; b < NBANK; b++) acc += d_banks[b*(6*64) + k];
        stat[k] = acc;
    }
    __syncthreads();
    if (tid < 192) {
        float sum, sq;
        if (tid < 64)       { sum = stat[0*64+tid];            sq = stat[1*64+tid]; }
        else if (tid < 128) { int c = tid-64;
                              sum = stat[0*64+c]-stat[2*64+c]; sq = stat[1*64+c]-stat[3*64+c]; }
        else                { int c = tid-128;
                              sum = stat[4*64+c];              sq = stat[5*64+c]; }
        float mu  = sum / (float)ROWS;
        float var = sq  / (float)ROWS - mu*mu;
        float sj  = gamma[tid] * rsqrtf(var + BN_EPS);
        s[tid]  = sj;
        tt[tid] = beta[tid] - mu*sj;
    }
    __syncthreads();
    for (int i = tid; i < 1536; i += 256) {
        int lane = i & 31;
        int ntp  = (i >> 5) & 3;
        int ks   = i >> 7;                 // 0..11
        int tig  = lane & 3, gid = lane >> 2;
        int j0   = ks*16 + tig*2;
        int n0   = ntp*16 + gid;
        uint4 v;
        v.x = pack_h2(W1[n0*192 + j0]       * s[j0],   W1[n0*192 + j0+1]     * s[j0+1]);
        v.y = pack_h2(W1[n0*192 + j0+8]     * s[j0+8], W1[n0*192 + j0+9]     * s[j0+9]);
        v.z = pack_h2(W1[(n0+8)*192 + j0]   * s[j0],   W1[(n0+8)*192 + j0+1] * s[j0+1]);
        v.w = pack_h2(W1[(n0+8)*192 + j0+8] * s[j0+8], W1[(n0+8)*192 + j0+9] * s[j0+9]);
        d_Wfrag[i] = v;
    }
    if (tid < 64) {
        float acc = b1[tid];
        for (int j = 0; j < 192; j++) acc += tt[j] * W1[tid*192 + j];
        d_bp[tid] = acc;
    }
}

__device__ __forceinline__ void mma16(float (&c)[4], const unsigned* a, unsigned b0, unsigned b1) {
    asm volatile("mma.sync.aligned.m16n8k16.row.col.f32.f16.f16.f32 "
        "{%0,%1,%2,%3}, {%4,%5,%6,%7}, {%8,%9}, {%0,%1,%2,%3};"
        : "+f"(c[0]), "+f"(c[1]), "+f"(c[2]), "+f"(c[3])
        : "r"(a[0]), "r"(a[1]), "r"(a[2]), "r"(a[3]), "r"(b0), "r"(b1));
}

// fp16 tensor-core GEMM+ReLU with smem-staged A + ldmatrix.
// Block = 8 warps = 256 rows; warp = 32 rows x 64 cols.
__global__ void __launch_bounds__(256) k_gemm(float* __restrict__ out) {
    __shared__ uint4 wfrag[1536];                 // 24KB
    __shared__ __align__(16) __half tile[256*64]; // 32KB, swizzled rows of 128B
    for (int i = threadIdx.x; i < 1536; i += 256) wfrag[i] = d_Wfrag[i];

    int lane = threadIdx.x & 31, warp = threadIdx.x >> 5;
    int gid = lane >> 2, tig = lane & 3;
    int r0 = blockIdx.x*256;
    uint32_t tbase = smem_u32(tile);

    float acc[2][8][4];
    #pragma unroll
    for (int mt = 0; mt < 2; mt++)
        #pragma unroll
        for (int nt = 0; nt < 8; nt++)
            #pragma unroll
            for (int q = 0; q < 4; q++) acc[mt][nt][q] = 0.f;

    #pragma unroll
    for (int c = 0; c < 3; c++) {
        __syncthreads();
        // stage 256x64 fp16 (uint4 coalesced), swizzled
        #pragma unroll
        for (int it = 0; it < 8; it++) {
            int idx = it*256 + threadIdx.x;      // 0..2047
            int row = idx >> 3, cg = (idx & 7)*8;
            int r = r0 + row;
            uint4 v = make_uint4(0,0,0,0);
            if (c == 0) {
                if (r < ROWS) v = *(const uint4*)(d_xh + (size_t)r*64 + cg);
            } else if (c == 1) {
                int re = r - NN;
                if (re >= 0 && r < ROWS) v = *(const uint4*)(d_xh + (size_t)re*64 + cg);
            } else {
                if (r < ROWS) v = *(const uint4*)(d_avgh + (size_t)r*64 + cg);
            }
            int off = row*128 + cg*2;
            *(uint4*)((char*)tile + (off ^ ((off >> 3) & 0x70))) = v;
        }
        __syncthreads();
        #pragma unroll
        for (int ksl = 0; ksl < 4; ksl++) {
            unsigned a[2][4];
            #pragma unroll
            for (int mt = 0; mt < 2; mt++) {
                int rr = warp*32 + mt*16 + (lane & 15);
                int cc = ksl*16 + ((lane >> 4) << 3);
                int off = rr*128 + cc*2;
                uint32_t ad = tbase + (off ^ ((off >> 3) & 0x70));
                asm volatile("ldmatrix.sync.aligned.m8n8.x4.shared.b16 {%0,%1,%2,%3}, [%4];"
                    : "=r"(a[mt][0]), "=r"(a[mt][1]), "=r"(a[mt][2]), "=r"(a[mt][3])
                    : "r"(ad));
            }
            const uint4* wb = &wfrag[((c*4 + ksl)*4)*32 + lane];
            #pragma unroll
            for (int ntp = 0; ntp < 4; ntp++) {
                uint4 b = wb[ntp*32];
                mma16(acc[0][2*ntp],   a[0], b.x, b.y);
                mma16(acc[1][2*ntp],   a[1], b.x, b.y);
                mma16(acc[0][2*ntp+1], a[0], b.z, b.w);
                mma16(acc[1][2*ntp+1], a[1], b.z, b.w);
            }
        }
    }

    float2* out2 = (float2*)out;
    const float2* bp2 = (const float2*)d_bp;
    int rbase = r0 + warp*32 + gid;
    #pragma unroll
    for (int mt = 0; mt < 2; mt++) {
        int ra = rbase + mt*16;
        int rb = ra + 8;
        #pragma unroll
        for (int nt = 0; nt < 8; nt++) {
            float2 bb = bp2[nt*4 + tig];
            if (ra < ROWS) {
                float2 o;
                o.x = fmaxf(acc[mt][nt][0] + bb.x, 0.f);
                o.y = fmaxf(acc[mt][nt][1] + bb.y, 0.f);
                out2[(size_t)ra*32 + nt*4 + tig] = o;
            }
            if (rb < ROWS) {
                float2 o;
                o.x = fmaxf(acc[mt][nt][2] + bb.x, 0.f);
                o.y = fmaxf(acc[mt][nt][3] + bb.y, 0.f);
                out2[(size_t)rb*32 + nt*4 + tig] = o;
            }
        }
    }
}

// ---------------- launch ----------------
// Fork-join: k_stage (node->fp16 + stats) is independent of the CSR chain
// (hist -> alloc -> fill), so it runs on a side stream in parallel.
extern "C" void kernel_launch(void* const* d_in, const int* in_sizes, int n_in,
                              void* d_out, int out_size) {
    const float* node  = (const float*)d_in[0];
    const float* ew    = (const float*)d_in[1];
    const float* W1    = (const float*)d_in[2];
    const float* b1    = (const float*)d_in[3];
    const float* gamma = (const float*)d_in[4];
    const float* beta  = (const float*)d_in[5];
    const int*   src   = (const int*)d_in[6];
    const int*   dst   = (const int*)d_in[7];
    float* out = (float*)d_out;

    static cudaStream_t s_side = nullptr;
    static cudaEvent_t  s_fork = nullptr, s_join = nullptr;
    if (s_side == nullptr) {
        cudaStreamCreateWithFlags(&s_side, cudaStreamNonBlocking);
        cudaEventCreateWithFlags(&s_fork, cudaEventDisableTiming);
        cudaEventCreateWithFlags(&s_join, cudaEventDisableTiming);
    }

    k_zero<<<SCAN_BLOCKS, 256>>>();

    // fork: side stream runs the staging pass concurrently with the CSR chain
    cudaEventRecord(s_fork, 0);
    cudaStreamWaitEvent(s_side, s_fork, 0);
    k_stage<<<512, 256, 0, s_side>>>(node);
    cudaEventRecord(s_join, s_side);

    k_hist<<<(EE+1023)/1024, 256>>>(ew, dst);
    k_alloc<<<SCAN_BLOCKS, 256>>>();
    k_fill<<<(EE+1023)/1024, 256>>>(ew, src, dst);

    // join: k_agg needs d_xh from k_stage
    cudaStreamWaitEvent(0, s_join, 0);

    k_agg<<<(2*NN+7)/8, 256>>>();
    k_finalize<<<1, 256>>>(W1, b1, gamma, beta);
    k_gemm<<<(ROWS+255)/256, 256>>>(out);
}

// round 13
// speedup vs baseline: 1.1494x; 1.1494x over previous
#include <cuda_runtime.h>
#include <cuda_fp16.h>
#include <cstdint>

#define TT 4
#define NN 50000
#define DH 64
#define EE 800000
#define ROWS (TT*NN)       // 200000
#define NBANK 64
#define BN_EPS 1e-5f
#define ZERO_BLOCKS 196
#define CAP 128            // per-node CSR bucket capacity (Poisson(16) -> never hit)

// ---------------- device scratch (static, no allocs) ----------------
__device__ __align__(16) __half d_xh[(size_t)ROWS*DH];    // fp16 node_data
__device__ __align__(16) __half d_avgh[(size_t)ROWS*DH];  // fp16 avg_neighbor
__device__ int   d_cnt[NN];
__device__ __align__(16) int2 d_csr[(size_t)NN*CAP];      // {src, w-bits} buckets
// banks: [bank][stat][col]: 0 sumAll,1 sqAll,2 sumLast,3 sqLast,4 sumAvg,5 sqAvg
__device__ float d_banks[NBANK*6*64];
__device__ __align__(16) uint4 d_Wfrag[1536];             // m16n8k16 B-fragment order
__device__ __align__(16) float d_bp[64];

__device__ __forceinline__ uint32_t smem_u32(const void* p) {
    uint32_t a;
    asm("{ .reg .u64 t; cvta.to.shared.u64 t, %1; cvt.u32.u64 %0, t; }" : "=r"(a) : "l"(p));
    return a;
}

// ---------------- kernels ----------------
__global__ void k_zero() {
    int i = blockIdx.x*256 + threadIdx.x;
    if (i < NN) d_cnt[i] = 0;
    if (i < NBANK*6*64) d_banks[i] = 0.f;
}

// direct-bucket CSR build: one pass, no hist/scan/alloc.
__global__ void k_fill(const float* __restrict__ ew, const int* __restrict__ src,
                       const int* __restrict__ dst) {
    int base = blockIdx.x*1024 + threadIdx.x;
    int ss[4], dd[4]; float ww[4]; bool v[4];
    #pragma unroll
    for (int k = 0; k < 4; k++) {
        int e = base + k*256;
        v[k] = (e < EE);
        if (v[k]) { ss[k] = src[e]; dd[k] = dst[e]; ww[k] = ew[e]; }
    }
    #pragma unroll
    for (int k = 0; k < 4; k++)
        if (v[k]) {
            int p = atomicAdd(&d_cnt[dd[k]], 1);
            if (p < CAP)
                d_csr[(size_t)dd[k]*CAP + p] = make_int2(ss[k], __float_as_int(ww[k]));
        }
}

// stage fp32 -> fp16 + column stats (single pass)
__global__ void __launch_bounds__(256) k_stage(const float* __restrict__ x) {
    int tid = blockIdx.x*256 + threadIdx.x;
    const int stride = 512*256;                  // divisible by 32
    const int lastBase = 3*NN*32;
    const float2* x2 = (const float2*)x;
    unsigned* xh2 = (unsigned*)d_xh;
    float s0=0.f,q0=0.f,l0=0.f,m0=0.f, s1=0.f,q1=0.f,l1=0.f,m1=0.f;
    for (int i = tid; i < ROWS*32; i += stride) {
        float2 v = x2[i];
        __half2 h = __floats2half2_rn(v.x, v.y);
        xh2[i] = *(unsigned*)&h;
        s0 += v.x; q0 += v.x*v.x; s1 += v.y; q1 += v.y*v.y;
        if (i >= lastBase) { l0 += v.x; m0 += v.x*v.x; l1 += v.y; m1 += v.y*v.y; }
    }
    __shared__ float sh[4][64];
    int col = (threadIdx.x & 31)*2;
    ((float*)sh)[threadIdx.x] = 0.f;
    __syncthreads();
    atomicAdd(&sh[0][col], s0); atomicAdd(&sh[0][col+1], s1);
    atomicAdd(&sh[1][col], q0); atomicAdd(&sh[1][col+1], q1);
    atomicAdd(&sh[2][col], l0); atomicAdd(&sh[2][col+1], l1);
    atomicAdd(&sh[3][col], m0); atomicAdd(&sh[3][col+1], m1);
    __syncthreads();
    if (threadIdx.x < 64) {
        float* b = d_banks + (blockIdx.x & (NBANK-1))*(6*64);
        atomicAdd(&b[0*64 + threadIdx.x], sh[0][threadIdx.x]);
        atomicAdd(&b[1*64 + threadIdx.x], sh[1][threadIdx.x]);
        atomicAdd(&b[2*64 + threadIdx.x], sh[2][threadIdx.x]);
        atomicAdd(&b[3*64 + threadIdx.x], sh[3][threadIdx.x]);
    }
}

// gather aggregation: warp per node, 4 timesteps, 8-unrolled batches.
// Z computed inline (sum of this node's edge weights; Z==0 <=> cnt==0).
__global__ void __launch_bounds__(256) k_agg() {
    int n    = blockIdx.x*8 + (threadIdx.x >> 5);
    int lane = threadIdx.x & 31;
    __shared__ float sv[64], sq[64];
    if (threadIdx.x < 64) { sv[threadIdx.x] = 0.f; sq[threadIdx.x] = 0.f; }
    __syncthreads();
    if (n < NN) {
        const unsigned* xh2 = (const unsigned*)d_xh;
        int cnt = d_cnt[n];
        const int2* seg = d_csr + (size_t)n*CAP;
        float zpart = 0.f;
        float2 a0 = make_float2(0.f,0.f), a1 = a0, a2 = a0, a3 = a0;
        for (int base = 0; base < cnt; base += 32) {
            int m = cnt - base; if (m > 32) m = 32;
            int2 sw = (lane < m) ? seg[base+lane] : make_int2(0,0);
            zpart += __int_as_float(sw.y);            // w=0 for inactive lanes
            int mp = (m + 7) & ~7;
            for (int kb = 0; kb < mp; kb += 8) {
                #pragma unroll
                for (int kk = 0; kk < 8; kk++) {
                    int k = kb + kk;
                    int   sk = __shfl_sync(0xffffffffu, sw.x, k);
                    float wk = __int_as_float(__shfl_sync(0xffffffffu, sw.y, k));
                    size_t ad = (size_t)sk*32 + lane;
                    unsigned u0 = xh2[ad];
                    unsigned u1 = xh2[(size_t)NN*32 + ad];
                    unsigned u2 = xh2[(size_t)2*NN*32 + ad];
                    unsigned u3 = xh2[(size_t)3*NN*32 + ad];
                    float2 v0 = __half22float2(*(__half2*)&u0);
                    float2 v1 = __half22float2(*(__half2*)&u1);
                    float2 v2 = __half22float2(*(__half2*)&u2);
                    float2 v3 = __half22float2(*(__half2*)&u3);
                    a0.x = fmaf(wk, v0.x, a0.x); a0.y = fmaf(wk, v0.y, a0.y);
                    a1.x = fmaf(wk, v1.x, a1.x); a1.y = fmaf(wk, v1.y, a1.y);
                    a2.x = fmaf(wk, v2.x, a2.x); a2.y = fmaf(wk, v2.y, a2.y);
                    a3.x = fmaf(wk, v3.x, a3.x); a3.y = fmaf(wk, v3.y, a3.y);
                }
            }
        }
        #pragma unroll
        for (int s = 16; s > 0; s >>= 1) zpart += __shfl_xor_sync(0xffffffffu, zpart, s);
        float inv = (cnt == 0) ? 1.f : 1.f/zpart;    // matches reference Z[Z==0]=1
        a0.x *= inv; a0.y *= inv; a1.x *= inv; a1.y *= inv;
        a2.x *= inv; a2.y *= inv; a3.x *= inv; a3.y *= inv;
        unsigned* av = (unsigned*)d_avgh;
        size_t nb = (size_t)n*32 + lane;
        __half2 h0 = __floats2half2_rn(a0.x, a0.y);
        __half2 h1 = __floats2half2_rn(a1.x, a1.y);
        __half2 h2 = __floats2half2_rn(a2.x, a2.y);
        __half2 h3 = __floats2half2_rn(a3.x, a3.y);
        av[nb]                   = *(unsigned*)&h0;
        av[(size_t)NN*32 + nb]   = *(unsigned*)&h1;
        av[(size_t)2*NN*32 + nb] = *(unsigned*)&h2;
        av[(size_t)3*NN*32 + nb] = *(unsigned*)&h3;
        atomicAdd(&sv[2*lane],   a0.x + a1.x + a2.x + a3.x);
        atomicAdd(&sv[2*lane+1], a0.y + a1.y + a2.y + a3.y);
        atomicAdd(&sq[2*lane],   a0.x*a0.x + a1.x*a1.x + a2.x*a2.x + a3.x*a3.x);
        atomicAdd(&sq[2*lane+1], a0.y*a0.y + a1.y*a1.y + a2.y*a2.y + a3.y*a3.y);
    }
    __syncthreads();
    if (threadIdx.x < 64) {
        float* b = d_banks + (blockIdx.x & (NBANK-1))*(6*64);
        atomicAdd(&b[4*64 + threadIdx.x], sv[threadIdx.x]);
        atomicAdd(&b[5*64 + threadIdx.x], sq[threadIdx.x]);
    }
}

__device__ __forceinline__ unsigned pack_h2(float lo, float hi) {
    __half2 h = __floats2half2_rn(lo, hi);
    return *(unsigned*)&h;
}

// fold BN into GEMM: fp16 fragment-packed W' (m16n8k16) and fp32 b'
__global__ void k_finalize(const float* __restrict__ W1, const float* __restrict__ b1,
                           const float* __restrict__ gamma, const float* __restrict__ beta) {
    __shared__ float stat[6*64];
    __shared__ float s[192];
    __shared__ float tt[192];
    int tid = threadIdx.x;
    for (int k = tid; k < 6*64; k += 256) {
        float acc = 0.f;
        for (int b = 0; b < NBANK; b++) acc += d_banks[b*(6*64) + k];
        stat[k] = acc;
    }
    __syncthreads();
    if (tid < 192) {
        float sum, sq;
        if (tid < 64)       { sum = stat[0*64+tid];            sq = stat[1*64+tid]; }
        else if (tid < 128) { int c = tid-64;
                              sum = stat[0*64+c]-stat[2*64+c]; sq = stat[1*64+c]-stat[3*64+c]; }
        else                { int c = tid-128;
                              sum = stat[4*64+c];              sq = stat[5*64+c]; }
        float mu  = sum / (float)ROWS;
        float var = sq  / (float)ROWS - mu*mu;
        float sj  = gamma[tid] * rsqrtf(var + BN_EPS);
        s[tid]  = sj;
        tt[tid] = beta[tid] - mu*sj;
    }
    __syncthreads();
    for (int i = tid; i < 1536; i += 256) {
        int lane = i & 31;
        int ntp  = (i >> 5) & 3;
        int ks   = i >> 7;                 // 0..11
        int tig  = lane & 3, gid = lane >> 2;
        int j0   = ks*16 + tig*2;
        int n0   = ntp*16 + gid;
        uint4 v;
        v.x = pack_h2(W1[n0*192 + j0]       * s[j0],   W1[n0*192 + j0+1]     * s[j0+1]);
        v.y = pack_h2(W1[n0*192 + j0+8]     * s[j0+8], W1[n0*192 + j0+9]     * s[j0+9]);
        v.z = pack_h2(W1[(n0+8)*192 + j0]   * s[j0],   W1[(n0+8)*192 + j0+1] * s[j0+1]);
        v.w = pack_h2(W1[(n0+8)*192 + j0+8] * s[j0+8], W1[(n0+8)*192 + j0+9] * s[j0+9]);
        d_Wfrag[i] = v;
    }
    if (tid < 64) {
        float acc = b1[tid];
        for (int j = 0; j < 192; j++) acc += tt[j] * W1[tid*192 + j];
        d_bp[tid] = acc;
    }
}

__device__ __forceinline__ void mma16(float (&c)[4], const unsigned* a, unsigned b0, unsigned b1) {
    asm volatile("mma.sync.aligned.m16n8k16.row.col.f32.f16.f16.f32 "
        "{%0,%1,%2,%3}, {%4,%5,%6,%7}, {%8,%9}, {%0,%1,%2,%3};"
        : "+f"(c[0]), "+f"(c[1]), "+f"(c[2]), "+f"(c[3])
        : "r"(a[0]), "r"(a[1]), "r"(a[2]), "r"(a[3]), "r"(b0), "r"(b1));
}

// fp16 tensor-core GEMM+ReLU with smem-staged A + ldmatrix.
// Block = 8 warps = 256 rows; warp = 32 rows x 64 cols.
__global__ void __launch_bounds__(256) k_gemm(float* __restrict__ out) {
    __shared__ uint4 wfrag[1536];                 // 24KB
    __shared__ __align__(16) __half tile[256*64]; // 32KB, swizzled rows of 128B
    for (int i = threadIdx.x; i < 1536; i += 256) wfrag[i] = d_Wfrag[i];

    int lane = threadIdx.x & 31, warp = threadIdx.x >> 5;
    int gid = lane >> 2, tig = lane & 3;
    int r0 = blockIdx.x*256;
    uint32_t tbase = smem_u32(tile);

    float acc[2][8][4];
    #pragma unroll
    for (int mt = 0; mt < 2; mt++)
        #pragma unroll
        for (int nt = 0; nt < 8; nt++)
            #pragma unroll
            for (int q = 0; q < 4; q++) acc[mt][nt][q] = 0.f;

    #pragma unroll
    for (int c = 0; c < 3; c++) {
        __syncthreads();
        // stage 256x64 fp16 (uint4 coalesced), swizzled
        #pragma unroll
        for (int it = 0; it < 8; it++) {
            int idx = it*256 + threadIdx.x;      // 0..2047
            int row = idx >> 3, cg = (idx & 7)*8;
            int r = r0 + row;
            uint4 v = make_uint4(0,0,0,0);
            if (c == 0) {
                if (r < ROWS) v = *(const uint4*)(d_xh + (size_t)r*64 + cg);
            } else if (c == 1) {
                int re = r - NN;
                if (re >= 0 && r < ROWS) v = *(const uint4*)(d_xh + (size_t)re*64 + cg);
            } else {
                if (r < ROWS) v = *(const uint4*)(d_avgh + (size_t)r*64 + cg);
            }
            int off = row*128 + cg*2;
            *(uint4*)((char*)tile + (off ^ ((off >> 3) & 0x70))) = v;
        }
        __syncthreads();
        #pragma unroll
        for (int ksl = 0; ksl < 4; ksl++) {
            unsigned a[2][4];
            #pragma unroll
            for (int mt = 0; mt < 2; mt++) {
                int rr = warp*32 + mt*16 + (lane & 15);
                int cc = ksl*16 + ((lane >> 4) << 3);
                int off = rr*128 + cc*2;
                uint32_t ad = tbase + (off ^ ((off >> 3) & 0x70));
                asm volatile("ldmatrix.sync.aligned.m8n8.x4.shared.b16 {%0,%1,%2,%3}, [%4];"
                    : "=r"(a[mt][0]), "=r"(a[mt][1]), "=r"(a[mt][2]), "=r"(a[mt][3])
                    : "r"(ad));
            }
            const uint4* wb = &wfrag[((c*4 + ksl)*4)*32 + lane];
            #pragma unroll
            for (int ntp = 0; ntp < 4; ntp++) {
                uint4 b = wb[ntp*32];
                mma16(acc[0][2*ntp],   a[0], b.x, b.y);
                mma16(acc[1][2*ntp],   a[1], b.x, b.y);
                mma16(acc[0][2*ntp+1], a[0], b.z, b.w);
                mma16(acc[1][2*ntp+1], a[1], b.z, b.w);
            }
        }
    }

    float2* out2 = (float2*)out;
    const float2* bp2 = (const float2*)d_bp;
    int rbase = r0 + warp*32 + gid;
    #pragma unroll
    for (int mt = 0; mt < 2; mt++) {
        int ra = rbase + mt*16;
        int rb = ra + 8;
        #pragma unroll
        for (int nt = 0; nt < 8; nt++) {
            float2 bb = bp2[nt*4 + tig];
            if (ra < ROWS) {
                float2 o;
                o.x = fmaxf(acc[mt][nt][0] + bb.x, 0.f);
                o.y = fmaxf(acc[mt][nt][1] + bb.y, 0.f);
                out2[(size_t)ra*32 + nt*4 + tig] = o;
            }
            if (rb < ROWS) {
                float2 o;
                o.x = fmaxf(acc[mt][nt][2] + bb.x, 0.f);
                o.y = fmaxf(acc[mt][nt][3] + bb.y, 0.f);
                out2[(size_t)rb*32 + nt*4 + tig] = o;
            }
        }
    }
}

// ---------------- launch ----------------
// Fork-join: k_stage is independent of the CSR build (zero -> fill), so it
// runs on a side stream in parallel. Join before k_agg (needs d_xh).
extern "C" void kernel_launch(void* const* d_in, const int* in_sizes, int n_in,
                              void* d_out, int out_size) {
    const float* node  = (const float*)d_in[0];
    const float* ew    = (const float*)d_in[1];
    const float* W1    = (const float*)d_in[2];
    const float* b1    = (const float*)d_in[3];
    const float* gamma = (const float*)d_in[4];
    const float* beta  = (const float*)d_in[5];
    const int*   src   = (const int*)d_in[6];
    const int*   dst   = (const int*)d_in[7];
    float* out = (float*)d_out;

    static cudaStream_t s_side = nullptr;
    static cudaEvent_t  s_fork = nullptr, s_join = nullptr;
    if (s_side == nullptr) {
        cudaStreamCreateWithFlags(&s_side, cudaStreamNonBlocking);
        cudaEventCreateWithFlags(&s_fork, cudaEventDisableTiming);
        cudaEventCreateWithFlags(&s_join, cudaEventDisableTiming);
    }

    k_zero<<<ZERO_BLOCKS, 256>>>();

    // fork: side stream runs the staging pass concurrently with the CSR build
    cudaEventRecord(s_fork, 0);
    cudaStreamWaitEvent(s_side, s_fork, 0);
    k_stage<<<512, 256, 0, s_side>>>(node);
    cudaEventRecord(s_join, s_side);

    k_fill<<<(EE+1023)/1024, 256>>>(ew, src, dst);

    // join: k_agg needs d_xh from k_stage
    cudaStreamWaitEvent(0, s_join, 0);

    k_agg<<<(NN+7)/8, 256>>>();
    k_finalize<<<1, 256>>>(W1, b1, gamma, beta);
    k_gemm<<<(ROWS+255)/256, 256>>>(out);
}

// round 14
// speedup vs baseline: 1.1784x; 1.0252x over previous
#include <cuda_runtime.h>
#include <cuda_fp16.h>
#include <cstdint>

#define TT 4
#define NN 50000
#define DH 64
#define EE 800000
#define ROWS (TT*NN)       // 200000
#define NBANK 64
#define BN_EPS 1e-5f
#define ZERO_BLOCKS 196
#define CAP 128            // per-node CSR bucket capacity (Poisson(16) -> never hit)

// ---------------- device scratch (static, no allocs) ----------------
__device__ __align__(16) __half d_xh[(size_t)ROWS*DH];    // fp16 node_data
__device__ __align__(16) __half d_avgh[(size_t)ROWS*DH];  // fp16 avg_neighbor
__device__ int   d_cnt[NN];
__device__ __align__(16) int2 d_csr[(size_t)NN*CAP];      // {src, w-bits} buckets
// banks: [bank][stat][col]: 0 sumAll,1 sqAll,2 sumLast,3 sqLast,4 sumAvg,5 sqAvg
__device__ float d_banks[NBANK*6*64];
__device__ __align__(16) uint4 d_Wfrag[1536];             // m16n8k16 B-fragment order
__device__ __align__(16) float d_bp[64];

__device__ __forceinline__ uint32_t smem_u32(const void* p) {
    uint32_t a;
    asm("{ .reg .u64 t; cvta.to.shared.u64 t, %1; cvt.u32.u64 %0, t; }" : "=r"(a) : "l"(p));
    return a;
}

// ---------------- kernels ----------------
__global__ void k_zero() {
    int i = blockIdx.x*256 + threadIdx.x;
    if (i < NN) d_cnt[i] = 0;
    if (i < NBANK*6*64) d_banks[i] = 0.f;
}

// direct-bucket CSR build: one pass, no hist/scan/alloc.
__global__ void k_fill(const float* __restrict__ ew, const int* __restrict__ src,
                       const int* __restrict__ dst) {
    int base = blockIdx.x*1024 + threadIdx.x;
    int ss[4], dd[4]; float ww[4]; bool v[4];
    #pragma unroll
    for (int k = 0; k < 4; k++) {
        int e = base + k*256;
        v[k] = (e < EE);
        if (v[k]) { ss[k] = src[e]; dd[k] = dst[e]; ww[k] = ew[e]; }
    }
    #pragma unroll
    for (int k = 0; k < 4; k++)
        if (v[k]) {
            int p = atomicAdd(&d_cnt[dd[k]], 1);
            if (p < CAP)
                d_csr[(size_t)dd[k]*CAP + p] = make_int2(ss[k], __float_as_int(ww[k]));
        }
}

// stage fp32 -> fp16 + column stats (single pass)
__global__ void __launch_bounds__(256) k_stage(const float* __restrict__ x) {
    int tid = blockIdx.x*256 + threadIdx.x;
    const int stride = 512*256;                  // divisible by 32
    const int lastBase = 3*NN*32;
    const float2* x2 = (const float2*)x;
    unsigned* xh2 = (unsigned*)d_xh;
    float s0=0.f,q0=0.f,l0=0.f,m0=0.f, s1=0.f,q1=0.f,l1=0.f,m1=0.f;
    for (int i = tid; i < ROWS*32; i += stride) {
        float2 v = x2[i];
        __half2 h = __floats2half2_rn(v.x, v.y);
        xh2[i] = *(unsigned*)&h;
        s0 += v.x; q0 += v.x*v.x; s1 += v.y; q1 += v.y*v.y;
        if (i >= lastBase) { l0 += v.x; m0 += v.x*v.x; l1 += v.y; m1 += v.y*v.y; }
    }
    __shared__ float sh[4][64];
    int col = (threadIdx.x & 31)*2;
    ((float*)sh)[threadIdx.x] = 0.f;
    __syncthreads();
    atomicAdd(&sh[0][col], s0); atomicAdd(&sh[0][col+1], s1);
    atomicAdd(&sh[1][col], q0); atomicAdd(&sh[1][col+1], q1);
    atomicAdd(&sh[2][col], l0); atomicAdd(&sh[2][col+1], l1);
    atomicAdd(&sh[3][col], m0); atomicAdd(&sh[3][col+1], m1);
    __syncthreads();
    if (threadIdx.x < 64) {
        float* b = d_banks + (blockIdx.x & (NBANK-1))*(6*64);
        atomicAdd(&b[0*64 + threadIdx.x], sh[0][threadIdx.x]);
        atomicAdd(&b[1*64 + threadIdx.x], sh[1][threadIdx.x]);
        atomicAdd(&b[2*64 + threadIdx.x], sh[2][threadIdx.x]);
        atomicAdd(&b[3*64 + threadIdx.x], sh[3][threadIdx.x]);
    }
}

// gather aggregation: warp per node, 4 timesteps.
// HFMA2 partial accumulation over 8-edge sub-batches, fp32 flush per batch.
// Z computed inline from fp32 weights (Z==0 <=> cnt==0).
__global__ void __launch_bounds__(256) k_agg() {
    int n    = blockIdx.x*8 + (threadIdx.x >> 5);
    int lane = threadIdx.x & 31;
    __shared__ float sv[64], sq[64];
    if (threadIdx.x < 64) { sv[threadIdx.x] = 0.f; sq[threadIdx.x] = 0.f; }
    __syncthreads();
    if (n < NN) {
        const unsigned* xh2 = (const unsigned*)d_xh;
        int cnt = d_cnt[n];
        if (cnt > CAP) cnt = CAP;                 // bucket overflow guard
        const int2* seg = d_csr + (size_t)n*CAP;
        float zpart = 0.f;
        float2 a0 = make_float2(0.f,0.f), a1 = a0, a2 = a0, a3 = a0;
        const __half2 hz = __floats2half2_rn(0.f, 0.f);
        for (int base = 0; base < cnt; base += 32) {
            int m = cnt - base; if (m > 32) m = 32;
            int2 sw = (lane < m) ? seg[base+lane] : make_int2(0,0);
            zpart += __int_as_float(sw.y);        // w=0 for inactive lanes
            int mp = (m + 7) & ~7;
            for (int kb = 0; kb < mp; kb += 8) {
                __half2 h0 = hz, h1 = hz, h2 = hz, h3 = hz;
                #pragma unroll
                for (int kk = 0; kk < 8; kk++) {
                    int k = kb + kk;
                    int   sk = __shfl_sync(0xffffffffu, sw.x, k);
                    float wk = __int_as_float(__shfl_sync(0xffffffffu, sw.y, k));
                    __half2 wh = __float2half2_rn(wk);
                    size_t ad = (size_t)sk*32 + lane;
                    unsigned u0 = xh2[ad];
                    unsigned u1 = xh2[(size_t)NN*32 + ad];
                    unsigned u2 = xh2[(size_t)2*NN*32 + ad];
                    unsigned u3 = xh2[(size_t)3*NN*32 + ad];
                    h0 = __hfma2(wh, *(__half2*)&u0, h0);
                    h1 = __hfma2(wh, *(__half2*)&u1, h1);
                    h2 = __hfma2(wh, *(__half2*)&u2, h2);
                    h3 = __hfma2(wh, *(__half2*)&u3, h3);
                }
                float2 f;
                f = __half22float2(h0); a0.x += f.x; a0.y += f.y;
                f = __half22float2(h1); a1.x += f.x; a1.y += f.y;
                f = __half22float2(h2); a2.x += f.x; a2.y += f.y;
                f = __half22float2(h3); a3.x += f.x; a3.y += f.y;
            }
        }
        #pragma unroll
        for (int s = 16; s > 0; s >>= 1) zpart += __shfl_xor_sync(0xffffffffu, zpart, s);
        float inv = (cnt == 0) ? 1.f : 1.f/zpart;    // matches reference Z[Z==0]=1
        a0.x *= inv; a0.y *= inv; a1.x *= inv; a1.y *= inv;
        a2.x *= inv; a2.y *= inv; a3.x *= inv; a3.y *= inv;
        unsigned* av = (unsigned*)d_avgh;
        size_t nb = (size_t)n*32 + lane;
        __half2 h0 = __floats2half2_rn(a0.x, a0.y);
        __half2 h1 = __floats2half2_rn(a1.x, a1.y);
        __half2 h2 = __floats2half2_rn(a2.x, a2.y);
        __half2 h3 = __floats2half2_rn(a3.x, a3.y);
        av[nb]                   = *(unsigned*)&h0;
        av[(size_t)NN*32 + nb]   = *(unsigned*)&h1;
        av[(size_t)2*NN*32 + nb] = *(unsigned*)&h2;
        av[(size_t)3*NN*32 + nb] = *(unsigned*)&h3;
        atomicAdd(&sv[2*lane],   a0.x + a1.x + a2.x + a3.x);
        atomicAdd(&sv[2*lane+1], a0.y + a1.y + a2.y + a3.y);
        atomicAdd(&sq[2*lane],   a0.x*a0.x + a1.x*a1.x + a2.x*a2.x + a3.x*a3.x);
        atomicAdd(&sq[2*lane+1], a0.y*a0.y + a1.y*a1.y + a2.y*a2.y + a3.y*a3.y);
    }
    __syncthreads();
    if (threadIdx.x < 64) {
        float* b = d_banks + (blockIdx.x & (NBANK-1))*(6*64);
        atomicAdd(&b[4*64 + threadIdx.x], sv[threadIdx.x]);
        atomicAdd(&b[5*64 + threadIdx.x], sq[threadIdx.x]);
    }
}

__device__ __forceinline__ unsigned pack_h2(float lo, float hi) {
    __half2 h = __floats2half2_rn(lo, hi);
    return *(unsigned*)&h;
}

// fold BN into GEMM: fp16 fragment-packed W' (m16n8k16) and fp32 b'
__global__ void k_finalize(const float* __restrict__ W1, const float* __restrict__ b1,
                           const float* __restrict__ gamma, const float* __restrict__ beta) {
    __shared__ float stat[6*64];
    __shared__ float s[192];
    __shared__ float tt[192];
    int tid = threadIdx.x;
    for (int k = tid; k < 6*64; k += 256) {
        float acc = 0.f;
        for (int b = 0; b < NBANK; b++) acc += d_banks[b*(6*64) + k];
        stat[k] = acc;
    }
    __syncthreads();
    if (tid < 192) {
        float sum, sq;
        if (tid < 64)       { sum = stat[0*64+tid];            sq = stat[1*64+tid]; }
        else if (tid < 128) { int c = tid-64;
                              sum = stat[0*64+c]-stat[2*64+c]; sq = stat[1*64+c]-stat[3*64+c]; }
        else                { int c = tid-128;
                              sum = stat[4*64+c];              sq = stat[5*64+c]; }
        float mu  = sum / (float)ROWS;
        float var = sq  / (float)ROWS - mu*mu;
        float sj  = gamma[tid] * rsqrtf(var + BN_EPS);
        s[tid]  = sj;
        tt[tid] = beta[tid] - mu*sj;
    }
    __syncthreads();
    for (int i = tid; i < 1536; i += 256) {
        int lane = i & 31;
        int ntp  = (i >> 5) & 3;
        int ks   = i >> 7;                 // 0..11
        int tig  = lane & 3, gid = lane >> 2;
        int j0   = ks*16 + tig*2;
        int n0   = ntp*16 + gid;
        uint4 v;
        v.x = pack_h2(W1[n0*192 + j0]       * s[j0],   W1[n0*192 + j0+1]     * s[j0+1]);
        v.y = pack_h2(W1[n0*192 + j0+8]     * s[j0+8], W1[n0*192 + j0+9]     * s[j0+9]);
        v.z = pack_h2(W1[(n0+8)*192 + j0]   * s[j0],   W1[(n0+8)*192 + j0+1] * s[j0+1]);
        v.w = pack_h2(W1[(n0+8)*192 + j0+8] * s[j0+8], W1[(n0+8)*192 + j0+9] * s[j0+9]);
        d_Wfrag[i] = v;
    }
    if (tid < 64) {
        float acc = b1[tid];
        for (int j = 0; j < 192; j++) acc += tt[j] * W1[tid*192 + j];
        d_bp[tid] = acc;
    }
}

__device__ __forceinline__ void mma16(float (&c)[4], const unsigned* a, unsigned b0, unsigned b1) {
    asm volatile("mma.sync.aligned.m16n8k16.row.col.f32.f16.f16.f32 "
        "{%0,%1,%2,%3}, {%4,%5,%6,%7}, {%8,%9}, {%0,%1,%2,%3};"
        : "+f"(c[0]), "+f"(c[1]), "+f"(c[2]), "+f"(c[3])
        : "r"(a[0]), "r"(a[1]), "r"(a[2]), "r"(a[3]), "r"(b0), "r"(b1));
}

// fp16 tensor-core GEMM+ReLU with smem-staged A + ldmatrix.
// Block = 8 warps = 256 rows; warp = 32 rows x 64 cols.
__global__ void __launch_bounds__(256) k_gemm(float* __restrict__ out) {
    __shared__ uint4 wfrag[1536];                 // 24KB
    __shared__ __align__(16) __half tile[256*64]; // 32KB, swizzled rows of 128B
    for (int i = threadIdx.x; i < 1536; i += 256) wfrag[i] = d_Wfrag[i];

    int lane = threadIdx.x & 31, warp = threadIdx.x >> 5;
    int gid = lane >> 2, tig = lane & 3;
    int r0 = blockIdx.x*256;
    uint32_t tbase = smem_u32(tile);

    float acc[2][8][4];
    #pragma unroll
    for (int mt = 0; mt < 2; mt++)
        #pragma unroll
        for (int nt = 0; nt < 8; nt++)
            #pragma unroll
            for (int q = 0; q < 4; q++) acc[mt][nt][q] = 0.f;

    #pragma unroll
    for (int c = 0; c < 3; c++) {
        __syncthreads();
        // stage 256x64 fp16 (uint4 coalesced), swizzled
        #pragma unroll
        for (int it = 0; it < 8; it++) {
            int idx = it*256 + threadIdx.x;      // 0..2047
            int row = idx >> 3, cg = (idx & 7)*8;
            int r = r0 + row;
            uint4 v = make_uint4(0,0,0,0);
            if (c == 0) {
                if (r < ROWS) v = *(const uint4*)(d_xh + (size_t)r*64 + cg);
            } else if (c == 1) {
                int re = r - NN;
                if (re >= 0 && r < ROWS) v = *(const uint4*)(d_xh + (size_t)re*64 + cg);
            } else {
                if (r < ROWS) v = *(const uint4*)(d_avgh + (size_t)r*64 + cg);
            }
            int off = row*128 + cg*2;
            *(uint4*)((char*)tile + (off ^ ((off >> 3) & 0x70))) = v;
        }
        __syncthreads();
        #pragma unroll
        for (int ksl = 0; ksl < 4; ksl++) {
            unsigned a[2][4];
            #pragma unroll
            for (int mt = 0; mt < 2; mt++) {
                int rr = warp*32 + mt*16 + (lane & 15);
                int cc = ksl*16 + ((lane >> 4) << 3);
                int off = rr*128 + cc*2;
                uint32_t ad = tbase + (off ^ ((off >> 3) & 0x70));
                asm volatile("ldmatrix.sync.aligned.m8n8.x4.shared.b16 {%0,%1,%2,%3}, [%4];"
                    : "=r"(a[mt][0]), "=r"(a[mt][1]), "=r"(a[mt][2]), "=r"(a[mt][3])
                    : "r"(ad));
            }
            const uint4* wb = &wfrag[((c*4 + ksl)*4)*32 + lane];
            #pragma unroll
            for (int ntp = 0; ntp < 4; ntp++) {
                uint4 b = wb[ntp*32];
                mma16(acc[0][2*ntp],   a[0], b.x, b.y);
                mma16(acc[1][2*ntp],   a[1], b.x, b.y);
                mma16(acc[0][2*ntp+1], a[0], b.z, b.w);
                mma16(acc[1][2*ntp+1], a[1], b.z, b.w);
            }
        }
    }

    float2* out2 = (float2*)out;
    const float2* bp2 = (const float2*)d_bp;
    int rbase = r0 + warp*32 + gid;
    #pragma unroll
    for (int mt = 0; mt < 2; mt++) {
        int ra = rbase + mt*16;
        int rb = ra + 8;
        #pragma unroll
        for (int nt = 0; nt < 8; nt++) {
            float2 bb = bp2[nt*4 + tig];
            if (ra < ROWS) {
                float2 o;
                o.x = fmaxf(acc[mt][nt][0] + bb.x, 0.f);
                o.y = fmaxf(acc[mt][nt][1] + bb.y, 0.f);
                out2[(size_t)ra*32 + nt*4 + tig] = o;
            }
            if (rb < ROWS) {
                float2 o;
                o.x = fmaxf(acc[mt][nt][2] + bb.x, 0.f);
                o.y = fmaxf(acc[mt][nt][3] + bb.y, 0.f);
                out2[(size_t)rb*32 + nt*4 + tig] = o;
            }
        }
    }
}

// ---------------- launch ----------------
// Fork-join: k_stage is independent of the CSR build (zero -> fill), so it
// runs on a side stream in parallel. Join before k_agg (needs d_xh).
extern "C" void kernel_launch(void* const* d_in, const int* in_sizes, int n_in,
                              void* d_out, int out_size) {
    const float* node  = (const float*)d_in[0];
    const float* ew    = (const float*)d_in[1];
    const float* W1    = (const float*)d_in[2];
    const float* b1    = (const float*)d_in[3];
    const float* gamma = (const float*)d_in[4];
    const float* beta  = (const float*)d_in[5];
    const int*   src   = (const int*)d_in[6];
    const int*   dst   = (const int*)d_in[7];
    float* out = (float*)d_out;

    static cudaStream_t s_side = nullptr;
    static cudaEvent_t  s_fork = nullptr, s_join = nullptr;
    if (s_side == nullptr) {
        cudaStreamCreateWithFlags(&s_side, cudaStreamNonBlocking);
        cudaEventCreateWithFlags(&s_fork, cudaEventDisableTiming);
        cudaEventCreateWithFlags(&s_join, cudaEventDisableTiming);
    }

    k_zero<<<ZERO_BLOCKS, 256>>>();

    // fork: side stream runs the staging pass concurrently with the CSR build
    cudaEventRecord(s_fork, 0);
    cudaStreamWaitEvent(s_side, s_fork, 0);
    k_stage<<<512, 256, 0, s_side>>>(node);
    cudaEventRecord(s_join, s_side);

    k_fill<<<(EE+1023)/1024, 256>>>(ew, src, dst);

    // join: k_agg needs d_xh from k_stage
    cudaStreamWaitEvent(0, s_join, 0);

    k_agg<<<(NN+7)/8, 256>>>();
    k_finalize<<<1, 256>>>(W1, b1, gamma, beta);
    k_gemm<<<(ROWS+255)/256, 256>>>(out);
}